// round 4
// baseline (speedup 1.0000x reference)
#include <cuda_runtime.h>
#include <cuda_bf16.h>
#include <cstdint>

// ---------------------------------------------------------------------------
// SAGE 2-layer forward, GB300 sm_103a (ptxas target is baseline sm_103:
// no tcgen05 -> tensor cores via mma.sync m16n8k16 bf16, 3-pass hi/lo split).
//   L1: h  = relu( mean_agg(x) @ W1l + b1 + x @ W1r )
//   L2: out= mean_agg(h@W2l) + b2 + h @ W2r       (project before scatter)
// edge_index is int32 on device.
// ---------------------------------------------------------------------------

#define N_NODES 50000
#define N_EDGES 800000
#define IN_C    128
#define HID_C   128
#define OUT_C   64

__device__ __align__(16) float g_msg1[(size_t)N_NODES * HID_C];
__device__ __align__(16) float g_deg [N_NODES];
__device__ __align__(16) float g_h   [(size_t)N_NODES * HID_C];
__device__ __align__(16) float g_c2  [(size_t)N_NODES * 128];   // [t=h@W2l | hr=h@W2r]
__device__ __align__(16) float g_msg2[(size_t)N_NODES * OUT_C];

// pre-split weights, [n][k] layout (bf16 hi / lo)
__device__ __align__(16) __nv_bfloat16 gW1hi[128 * 256];
__device__ __align__(16) __nv_bfloat16 gW1lo[128 * 256];
__device__ __align__(16) __nv_bfloat16 gW2hi[128 * 128];
__device__ __align__(16) __nv_bfloat16 gW2lo[128 * 128];

// ---------------- helpers ----------------------------------------------------
__device__ __forceinline__ void red_add_v4(float* addr, float4 v) {
    asm volatile("red.global.add.v4.f32 [%0], {%1,%2,%3,%4};"
                 :: "l"(addr), "f"(v.x), "f"(v.y), "f"(v.z), "f"(v.w) : "memory");
}
__device__ __forceinline__ uint32_t smem_u32(const void* p) {
    uint32_t a;
    asm("{ .reg .u64 t; cvta.to.shared.u64 t, %1; cvt.u32.u64 %0, t; }" : "=r"(a) : "l"(p));
    return a;
}
__device__ __forceinline__ void split2(float f0, float f1, uint32_t& hi, uint32_t& lo) {
    __nv_bfloat16 h0 = __float2bfloat16(f0);
    __nv_bfloat16 h1 = __float2bfloat16(f1);
    __nv_bfloat16 l0 = __float2bfloat16(f0 - __bfloat162float(h0));
    __nv_bfloat16 l1 = __float2bfloat16(f1 - __bfloat162float(h1));
    hi = ((uint32_t)__bfloat16_as_ushort(h1) << 16) | __bfloat16_as_ushort(h0);
    lo = ((uint32_t)__bfloat16_as_ushort(l1) << 16) | __bfloat16_as_ushort(l0);
}
__device__ __forceinline__ void ldsm4(uint32_t* r, uint32_t addr) {
    asm volatile("ldmatrix.sync.aligned.m8n8.x4.shared.b16 {%0,%1,%2,%3}, [%4];"
                 : "=r"(r[0]), "=r"(r[1]), "=r"(r[2]), "=r"(r[3]) : "r"(addr));
}
__device__ __forceinline__ void mma16816(float* d, const uint32_t* a, uint32_t b0, uint32_t b1) {
    asm volatile(
        "mma.sync.aligned.m16n8k16.row.col.f32.bf16.bf16.f32 "
        "{%0,%1,%2,%3}, {%4,%5,%6,%7}, {%8,%9}, {%0,%1,%2,%3};"
        : "+f"(d[0]), "+f"(d[1]), "+f"(d[2]), "+f"(d[3])
        : "r"(a[0]), "r"(a[1]), "r"(a[2]), "r"(a[3]), "r"(b0), "r"(b1));
}

// ---------------------------------------------------------------------------
__global__ void zero_kernel() {
    const float4 z = make_float4(0.f, 0.f, 0.f, 0.f);
    int tid = blockIdx.x * blockDim.x + threadIdx.x;
    int stride = gridDim.x * blockDim.x;
    float4* m1 = (float4*)g_msg1;
    for (int i = tid; i < N_NODES * HID_C / 4; i += stride) m1[i] = z;
    float4* m2 = (float4*)g_msg2;
    for (int i = tid; i < N_NODES * OUT_C / 4; i += stride) m2[i] = z;
    float4* dg = (float4*)g_deg;
    for (int i = tid; i < N_NODES / 4; i += stride) dg[i] = z;
}

// Build [n][k] bf16 hi/lo weight matrices.
__global__ void prep_weights(const float* __restrict__ W1l, const float* __restrict__ W1r,
                             const float* __restrict__ W2l, const float* __restrict__ W2r) {
    int idx = blockIdx.x * blockDim.x + threadIdx.x;
    if (idx < 128 * 256) {                       // gemm1 weights: K=256
        int n = idx >> 8, k = idx & 255;
        float v = (k < 128) ? __ldg(W1l + (size_t)k * 128 + n)
                            : __ldg(W1r + (size_t)(k - 128) * 128 + n);
        __nv_bfloat16 h = __float2bfloat16(v);
        gW1hi[idx] = h;
        gW1lo[idx] = __float2bfloat16(v - __bfloat162float(h));
    }
    if (idx < 128 * 128) {                       // gemm2 weights: K=128, n = [W2l | W2r]
        int n = idx >> 7, k = idx & 127;
        float v = (n < 64) ? __ldg(W2l + (size_t)k * 64 + n)
                           : __ldg(W2r + (size_t)k * 64 + (n - 64));
        __nv_bfloat16 h = __float2bfloat16(v);
        gW2hi[idx] = h;
        gW2lo[idx] = __float2bfloat16(v - __bfloat162float(h));
    }
}

// ---------------------------------------------------------------------------
__global__ void scatter1_kernel(const float* __restrict__ x, const int* __restrict__ ei) {
    int gtid = blockIdx.x * blockDim.x + threadIdx.x;
    int e = gtid >> 5, lane = gtid & 31;
    if (e >= N_EDGES) return;
    int src = __ldg(ei + e);
    int dst = __ldg(ei + N_EDGES + e);
    if ((unsigned)src >= N_NODES || (unsigned)dst >= N_NODES) return;
    float4 v = __ldg((const float4*)(x + (size_t)src * IN_C) + lane);
    red_add_v4(g_msg1 + (size_t)dst * HID_C + lane * 4, v);
    if (lane == 0) atomicAdd(&g_deg[dst], 1.0f);
}

__global__ void scatter2_kernel(const int* __restrict__ ei) {
    int gtid = blockIdx.x * blockDim.x + threadIdx.x;
    int e = gtid >> 4, l = gtid & 15;
    if (e >= N_EDGES) return;
    int src = __ldg(ei + e);
    int dst = __ldg(ei + N_EDGES + e);
    if ((unsigned)src >= N_NODES || (unsigned)dst >= N_NODES) return;
    float4 v = __ldg((const float4*)(g_c2 + (size_t)src * 128) + l);
    red_add_v4(g_msg2 + (size_t)dst * OUT_C + l * 4, v);
}

// ---------------------------------------------------------------------------
// Tensor-core GEMM (mma.sync bf16, hi/lo split, fp32 acc).
// Block tile 128(M) x 128(N), 8 warps (4 over M x 2 over N -> warp 32x64).
// KIND 1: A = [msg1*rdeg | x] (K=256), epilogue bias+relu -> g_h
// KIND 2: A = g_h (K=128),            epilogue raw       -> g_c2
// ---------------------------------------------------------------------------
#define A_STRIDE 72   // bf16 elements per smem row (144B = 9 x 16B -> ldmatrix conflict-free)

template <int KIND>
__device__ __forceinline__ void gemm_mma_body(const float* __restrict__ xin,
                                              const __nv_bfloat16* __restrict__ Whi,
                                              const __nv_bfloat16* __restrict__ Wlo,
                                              const float* __restrict__ bias) {
    constexpr int K_TOTAL = (KIND == 1) ? 256 : 128;

    __shared__ __nv_bfloat16 sAhi[128 * A_STRIDE];
    __shared__ __nv_bfloat16 sAlo[128 * A_STRIDE];
    __shared__ float rdeg_s[128];

    const int tid   = threadIdx.x;
    const int wid   = tid >> 5;
    const int lane  = tid & 31;
    const int warp_m = wid & 3;        // 0..3 -> 32-row slab
    const int warp_n = wid >> 2;       // 0..1 -> 64-col slab
    const int rowBase = blockIdx.x * 128;

    if (KIND == 1 && tid < 128) {
        int r = rowBase + tid;
        float dv = (r < N_NODES) ? g_deg[r] : 1.0f;
        rdeg_s[tid] = 1.0f / fmaxf(dv, 1.0f);
    }

    float acc[2][8][4];
    #pragma unroll
    for (int mt = 0; mt < 2; ++mt)
        #pragma unroll
        for (int nt = 0; nt < 8; ++nt)
            #pragma unroll
            for (int q = 0; q < 4; ++q) acc[mt][nt][q] = 0.f;

    const uint32_t sAhi_u = smem_u32(sAhi);
    const uint32_t sAlo_u = smem_u32(sAlo);

    for (int kb = 0; kb < K_TOTAL; kb += 64) {
        __syncthreads();
        // ---- stage A chunk: 128 rows x 64 k, fp32 -> bf16 hi/lo
        #pragma unroll
        for (int it = 0; it < 8; ++it) {
            int fid = tid + it * 256;       // 0..2047
            int row = fid >> 4;             // 0..127
            int c4  = fid & 15;             // float4 within row
            int gr  = rowBase + row;
            float4 v = make_float4(0.f, 0.f, 0.f, 0.f);
            if (gr < N_NODES) {
                if (KIND == 1) {
                    if (kb < 128) {
                        v = *(const float4*)(g_msg1 + (size_t)gr * 128 + kb + c4 * 4);
                        float s = rdeg_s[row];
                        v.x *= s; v.y *= s; v.z *= s; v.w *= s;
                    } else {
                        v = __ldg((const float4*)(xin + (size_t)gr * 128 + (kb - 128) + c4 * 4));
                    }
                } else {
                    v = *(const float4*)(g_h + (size_t)gr * 128 + kb + c4 * 4);
                }
            }
            uint32_t h01, l01, h23, l23;
            split2(v.x, v.y, h01, l01);
            split2(v.z, v.w, h23, l23);
            int eoff = row * A_STRIDE + c4 * 4;
            *(uint32_t*)((char*)sAhi + eoff * 2)     = h01;
            *(uint32_t*)((char*)sAhi + eoff * 2 + 4) = h23;
            *(uint32_t*)((char*)sAlo + eoff * 2)     = l01;
            *(uint32_t*)((char*)sAlo + eoff * 2 + 4) = l23;
        }
        __syncthreads();

        // ---- 4 k16 steps within this 64-k chunk
        #pragma unroll
        for (int ks = 0; ks < 4; ++ks) {
            // A fragments via ldmatrix.x4 (two 16x16 tiles per warp, hi + lo)
            uint32_t ahi[2][4], alo[2][4];
            #pragma unroll
            for (int mt = 0; mt < 2; ++mt) {
                int row = warp_m * 32 + mt * 16 + (lane & 15);
                int koff = ks * 16 + (lane >> 4) * 8;
                uint32_t byteoff = (uint32_t)(row * A_STRIDE + koff) * 2;
                ldsm4(ahi[mt], sAhi_u + byteoff);
                ldsm4(alo[mt], sAlo_u + byteoff);
            }
            // B fragments from global (bf16x2 packed, [n][k] layout) + MMAs
            #pragma unroll
            for (int nt = 0; nt < 8; ++nt) {
                int n  = warp_n * 64 + nt * 8 + (lane >> 2);
                int ke = kb + ks * 16 + (lane & 3) * 2;
                const char* ph = (const char*)(Whi + (size_t)n * K_TOTAL + ke);
                const char* pl = (const char*)(Wlo + (size_t)n * K_TOTAL + ke);
                uint32_t bh0 = __ldg((const uint32_t*)ph);
                uint32_t bh1 = __ldg((const uint32_t*)(ph + 16));
                uint32_t bl0 = __ldg((const uint32_t*)pl);
                uint32_t bl1 = __ldg((const uint32_t*)(pl + 16));
                #pragma unroll
                for (int mt = 0; mt < 2; ++mt) {
                    mma16816(acc[mt][nt], ahi[mt], bh0, bh1);   // Ahi*Bhi
                    mma16816(acc[mt][nt], ahi[mt], bl0, bl1);   // Ahi*Blo
                    mma16816(acc[mt][nt], alo[mt], bh0, bh1);   // Alo*Bhi
                }
            }
        }
    }

    // ---- epilogue: c-frag (m16n8): rows lane>>2 (+8), cols (lane&3)*2 (+1)
    #pragma unroll
    for (int mt = 0; mt < 2; ++mt) {
        int r0 = rowBase + warp_m * 32 + mt * 16 + (lane >> 2);
        #pragma unroll
        for (int nt = 0; nt < 8; ++nt) {
            int col = warp_n * 64 + nt * 8 + (lane & 3) * 2;
            float v0 = acc[mt][nt][0], v1 = acc[mt][nt][1];
            float v2 = acc[mt][nt][2], v3 = acc[mt][nt][3];
            if (KIND == 1) {
                float b0 = __ldg(bias + col), b1 = __ldg(bias + col + 1);
                v0 = fmaxf(v0 + b0, 0.f); v1 = fmaxf(v1 + b1, 0.f);
                v2 = fmaxf(v2 + b0, 0.f); v3 = fmaxf(v3 + b1, 0.f);
            }
            float* dst = (KIND == 1) ? g_h : g_c2;
            if (r0 < N_NODES)
                *(float2*)(dst + (size_t)r0 * 128 + col) = make_float2(v0, v1);
            if (r0 + 8 < N_NODES)
                *(float2*)(dst + (size_t)(r0 + 8) * 128 + col) = make_float2(v2, v3);
        }
    }
}

__global__ void __launch_bounds__(256) gemm1_mma(const float* __restrict__ x,
                                                 const float* __restrict__ b1) {
    gemm_mma_body<1>(x, gW1hi, gW1lo, b1);
}
__global__ void __launch_bounds__(256) gemm2_mma() {
    gemm_mma_body<2>(nullptr, gW2hi, gW2lo, nullptr);
}

// ---------------------------------------------------------------------------
__global__ void final_kernel(float* __restrict__ out, const float* __restrict__ b2) {
    int i = blockIdx.x * blockDim.x + threadIdx.x;
    if (i >= N_NODES * OUT_C) return;
    int n = i >> 6, j = i & 63;
    float d = fmaxf(g_deg[n], 1.0f);
    out[i] = g_msg2[i] / d + __ldg(b2 + j) + g_c2[(size_t)n * 128 + 64 + j];
}

// ---------------------------------------------------------------------------
extern "C" void kernel_launch(void* const* d_in, const int* in_sizes, int n_in,
                              void* d_out, int out_size) {
    const float* x   = (const float*)d_in[0];
    const int*   ei  = (const int*)d_in[1];
    const float* W1l = (const float*)d_in[2];
    const float* b1  = (const float*)d_in[3];
    const float* W1r = (const float*)d_in[4];
    const float* W2l = (const float*)d_in[5];
    const float* b2  = (const float*)d_in[6];
    const float* W2r = (const float*)d_in[7];
    float* out = (float*)d_out;

    zero_kernel<<<2048, 256>>>();
    prep_weights<<<128, 256>>>(W1l, W1r, W2l, W2r);
    scatter1_kernel<<<(N_EDGES * 32) / 256, 256>>>(x, ei);

    const int gemmBlocks = (N_NODES + 127) / 128;  // 391
    gemm1_mma<<<gemmBlocks, 256>>>(x, b1);
    gemm2_mma<<<gemmBlocks, 256>>>();

    scatter2_kernel<<<(N_EDGES * 16) / 256, 256>>>(ei);
    final_kernel<<<(N_NODES * OUT_C + 255) / 256, 256>>>(out, b2);
}

// round 5
// speedup vs baseline: 1.3725x; 1.3725x over previous
#include <cuda_runtime.h>
#include <cuda_bf16.h>
#include <cstdint>

// ---------------------------------------------------------------------------
// SAGE 2-layer forward, GB300 (ptxas target sm_103 baseline: no tcgen05).
// GEMMs: mma.sync m16n8k16 bf16, 3-pass hi/lo split (AhBh+AhBl+AlBh), fp32 acc.
//   - 64x128 CTA tile, 2 CTAs/SM, software-pipelined A staging
//   - B as precomputed MMA-ready fragments (1x LDG.128 per tile per k-step)
// edge_index is int32 on device.
// ---------------------------------------------------------------------------

#define N_NODES 50000
#define N_EDGES 800000
#define IN_C    128
#define HID_C   128
#define OUT_C   64

__device__ __align__(16) float g_msg1[(size_t)N_NODES * HID_C];
__device__ __align__(16) float g_deg [N_NODES];
__device__ __align__(16) float g_h   [(size_t)N_NODES * HID_C];
__device__ __align__(16) float g_c2  [(size_t)N_NODES * 128];   // [t=h@W2l | hr=h@W2r]
__device__ __align__(16) float g_msg2[(size_t)N_NODES * OUT_C];

// Precomputed B fragments: uint4 {bh0, bh1, bl0, bl1} per (n_tile, ks, lane).
// gemm1: 16 n_tiles x 16 ks x 32 lanes; gemm2: 16 x 8 x 32.
__device__ __align__(16) uint4 gW1frag[16 * 16 * 32];
__device__ __align__(16) uint4 gW2frag[16 * 8 * 32];

// ---------------- helpers ----------------------------------------------------
__device__ __forceinline__ void red_add_v4(float* addr, float4 v) {
    asm volatile("red.global.add.v4.f32 [%0], {%1,%2,%3,%4};"
                 :: "l"(addr), "f"(v.x), "f"(v.y), "f"(v.z), "f"(v.w) : "memory");
}
__device__ __forceinline__ uint32_t smem_u32(const void* p) {
    uint32_t a;
    asm("{ .reg .u64 t; cvta.to.shared.u64 t, %1; cvt.u32.u64 %0, t; }" : "=r"(a) : "l"(p));
    return a;
}
__device__ __forceinline__ void split2(float f0, float f1, uint32_t& hi, uint32_t& lo) {
    __nv_bfloat16 h0 = __float2bfloat16(f0);
    __nv_bfloat16 h1 = __float2bfloat16(f1);
    __nv_bfloat16 l0 = __float2bfloat16(f0 - __bfloat162float(h0));
    __nv_bfloat16 l1 = __float2bfloat16(f1 - __bfloat162float(h1));
    hi = ((uint32_t)__bfloat16_as_ushort(h1) << 16) | __bfloat16_as_ushort(h0);
    lo = ((uint32_t)__bfloat16_as_ushort(l1) << 16) | __bfloat16_as_ushort(l0);
}
__device__ __forceinline__ void ldsm4(uint32_t* r, uint32_t addr) {
    asm volatile("ldmatrix.sync.aligned.m8n8.x4.shared.b16 {%0,%1,%2,%3}, [%4];"
                 : "=r"(r[0]), "=r"(r[1]), "=r"(r[2]), "=r"(r[3]) : "r"(addr));
}
__device__ __forceinline__ void mma16816(float* d, const uint32_t* a, uint32_t b0, uint32_t b1) {
    asm volatile(
        "mma.sync.aligned.m16n8k16.row.col.f32.bf16.bf16.f32 "
        "{%0,%1,%2,%3}, {%4,%5,%6,%7}, {%8,%9}, {%0,%1,%2,%3};"
        : "+f"(d[0]), "+f"(d[1]), "+f"(d[2]), "+f"(d[3])
        : "r"(a[0]), "r"(a[1]), "r"(a[2]), "r"(a[3]), "r"(b0), "r"(b1));
}

// ---------------------------------------------------------------------------
__global__ void zero_kernel() {
    const float4 z = make_float4(0.f, 0.f, 0.f, 0.f);
    int tid = blockIdx.x * blockDim.x + threadIdx.x;
    int stride = gridDim.x * blockDim.x;
    float4* m1 = (float4*)g_msg1;
    for (int i = tid; i < N_NODES * HID_C / 4; i += stride) m1[i] = z;
    float4* m2 = (float4*)g_msg2;
    for (int i = tid; i < N_NODES * OUT_C / 4; i += stride) m2[i] = z;
    float4* dg = (float4*)g_deg;
    for (int i = tid; i < N_NODES / 4; i += stride) dg[i] = z;
}

// Build MMA-ready B fragments.
// b-frag for mma.m16n8k16.row.col, thread=lane: n = tile*8 + lane/4,
// k0 = ks*16 + (lane%4)*2; b0 covers {k0,k0+1}, b1 covers {k0+8,k0+9}.
__global__ void prep_weights(const float* __restrict__ W1l, const float* __restrict__ W1r,
                             const float* __restrict__ W2l, const float* __restrict__ W2r) {
    int idx = blockIdx.x * blockDim.x + threadIdx.x;
    int total1 = 16 * 16 * 32;
    int total2 = 16 * 8 * 32;
    if (idx < total1) {
        int lane = idx & 31;
        int ks   = (idx >> 5) & 15;
        int ntl  = idx >> 9;
        int n  = ntl * 8 + (lane >> 2);
        int k0 = ks * 16 + (lane & 3) * 2;
        float f[4];
        #pragma unroll
        for (int q = 0; q < 4; ++q) {
            int k = k0 + (q >> 1) * 8 + (q & 1);
            f[q] = (k < 128) ? __ldg(W1l + (size_t)k * 128 + n)
                             : __ldg(W1r + (size_t)(k - 128) * 128 + n);
        }
        uint4 r;
        split2(f[0], f[1], r.x, r.z);
        split2(f[2], f[3], r.y, r.w);
        gW1frag[idx] = r;
    } else if (idx < total1 + total2) {
        int j = idx - total1;
        int lane = j & 31;
        int ks   = (j >> 5) & 7;
        int ntl  = j >> 8;
        int n  = ntl * 8 + (lane >> 2);
        int k0 = ks * 16 + (lane & 3) * 2;
        float f[4];
        #pragma unroll
        for (int q = 0; q < 4; ++q) {
            int k = k0 + (q >> 1) * 8 + (q & 1);
            f[q] = (n < 64) ? __ldg(W2l + (size_t)k * 64 + n)
                            : __ldg(W2r + (size_t)k * 64 + (n - 64));
        }
        uint4 r;
        split2(f[0], f[1], r.x, r.z);
        split2(f[2], f[3], r.y, r.w);
        gW2frag[j] = r;
    }
}

// ---------------------------------------------------------------------------
__global__ void scatter1_kernel(const float* __restrict__ x, const int* __restrict__ ei) {
    int gtid = blockIdx.x * blockDim.x + threadIdx.x;
    int e = gtid >> 5, lane = gtid & 31;
    if (e >= N_EDGES) return;
    int src = __ldg(ei + e);
    int dst = __ldg(ei + N_EDGES + e);
    if ((unsigned)src >= N_NODES || (unsigned)dst >= N_NODES) return;
    float4 v = __ldg((const float4*)(x + (size_t)src * IN_C) + lane);
    red_add_v4(g_msg1 + (size_t)dst * HID_C + lane * 4, v);
    if (lane == 0) atomicAdd(&g_deg[dst], 1.0f);
}

__global__ void scatter2_kernel(const int* __restrict__ ei) {
    int gtid = blockIdx.x * blockDim.x + threadIdx.x;
    int e = gtid >> 4, l = gtid & 15;
    if (e >= N_EDGES) return;
    int src = __ldg(ei + e);
    int dst = __ldg(ei + N_EDGES + e);
    if ((unsigned)src >= N_NODES || (unsigned)dst >= N_NODES) return;
    float4 v = __ldg((const float4*)(g_c2 + (size_t)src * 128) + l);
    red_add_v4(g_msg2 + (size_t)dst * OUT_C + l * 4, v);
}

// ---------------------------------------------------------------------------
// Tensor-core GEMM: 64(M) x 128(N) CTA tile, 256 thr, 8 warps
// warp_m in {0,1} (32 rows), warp_n in {0..3} (32 cols -> 4 n-tiles of 8).
// KIND 1: A = [msg1*rdeg | x] (K=256), epilogue bias+relu -> g_h
// KIND 2: A = g_h (K=128),            epilogue raw       -> g_c2
// ---------------------------------------------------------------------------
#define A_STRIDE 72   // bf16 per smem row (144B -> ldmatrix conflict-free)

template <int KIND>
__device__ __forceinline__ void gemm_mma_body(const float* __restrict__ xin,
                                              const uint4* __restrict__ Bfrag,
                                              const float* __restrict__ bias) {
    constexpr int K_TOTAL = (KIND == 1) ? 256 : 128;
    constexpr int NKS     = K_TOTAL / 16;
    constexpr int NCHUNK  = K_TOTAL / 64;

    __shared__ __nv_bfloat16 sAhi[2][64 * A_STRIDE];
    __shared__ __nv_bfloat16 sAlo[2][64 * A_STRIDE];
    __shared__ float rdeg_s[64];

    const int tid    = threadIdx.x;
    const int wid    = tid >> 5;
    const int lane   = tid & 31;
    const int warp_m = wid & 1;        // 0..1 -> 32-row slab
    const int warp_n = wid >> 1;       // 0..3 -> 32-col slab
    const int rowBase = blockIdx.x * 64;

    if (KIND == 1 && tid < 64) {
        int r = rowBase + tid;
        float dv = (r < N_NODES) ? g_deg[r] : 1.0f;
        rdeg_s[tid] = 1.0f / fmaxf(dv, 1.0f);
    }

    // staging indices for this thread (4 float4 per chunk)
    // fid = tid + it*256 ; row = fid>>4 (0..63) ; c4 = fid&15
    float4 pf[4];

    auto load_chunk = [&](int kb) {
        #pragma unroll
        for (int it = 0; it < 4; ++it) {
            int fid = tid + it * 256;
            int row = fid >> 4;
            int c4  = fid & 15;
            int gr  = rowBase + row;
            float4 v = make_float4(0.f, 0.f, 0.f, 0.f);
            if (gr < N_NODES) {
                if (KIND == 1) {
                    if (kb < 128) {
                        v = *(const float4*)(g_msg1 + (size_t)gr * 128 + kb + c4 * 4);
                    } else {
                        v = __ldg((const float4*)(xin + (size_t)gr * 128 + (kb - 128) + c4 * 4));
                    }
                } else {
                    v = *(const float4*)(g_h + (size_t)gr * 128 + kb + c4 * 4);
                }
            }
            pf[it] = v;
        }
    };
    auto store_chunk = [&](int buf, int kb) {
        #pragma unroll
        for (int it = 0; it < 4; ++it) {
            int fid = tid + it * 256;
            int row = fid >> 4;
            int c4  = fid & 15;
            float4 v = pf[it];
            if (KIND == 1 && kb < 128) {
                float s = rdeg_s[row];
                v.x *= s; v.y *= s; v.z *= s; v.w *= s;
            }
            uint32_t h01, l01, h23, l23;
            split2(v.x, v.y, h01, l01);
            split2(v.z, v.w, h23, l23);
            int eoff = row * A_STRIDE + c4 * 4;
            *(uint32_t*)((char*)sAhi[buf] + eoff * 2)     = h01;
            *(uint32_t*)((char*)sAhi[buf] + eoff * 2 + 4) = h23;
            *(uint32_t*)((char*)sAlo[buf] + eoff * 2)     = l01;
            *(uint32_t*)((char*)sAlo[buf] + eoff * 2 + 4) = l23;
        }
    };

    float acc[2][4][4];
    #pragma unroll
    for (int mt = 0; mt < 2; ++mt)
        #pragma unroll
        for (int nt = 0; nt < 4; ++nt)
            #pragma unroll
            for (int q = 0; q < 4; ++q) acc[mt][nt][q] = 0.f;

    // prologue: stage chunk 0
    load_chunk(0);
    __syncthreads();          // rdeg_s ready before store_chunk scales
    store_chunk(0, 0);
    __syncthreads();

    const uint4* bptr = Bfrag + ((size_t)warp_n * 4 * NKS) * 32 + lane;

    for (int c = 0; c < NCHUNK; ++c) {
        int buf = c & 1;
        if (c + 1 < NCHUNK) load_chunk((c + 1) * 64);   // prefetch (overlaps MMAs)

        const uint32_t sAhi_u = smem_u32(sAhi[buf]);
        const uint32_t sAlo_u = smem_u32(sAlo[buf]);

        #pragma unroll
        for (int ks = 0; ks < 4; ++ks) {
            int kks = c * 4 + ks;
            uint32_t ahi[2][4], alo[2][4];
            #pragma unroll
            for (int mt = 0; mt < 2; ++mt) {
                int row = warp_m * 32 + mt * 16 + (lane & 15);
                int koff = ks * 16 + (lane >> 4) * 8;
                uint32_t byteoff = (uint32_t)(row * A_STRIDE + koff) * 2;
                ldsm4(ahi[mt], sAhi_u + byteoff);
                ldsm4(alo[mt], sAlo_u + byteoff);
            }
            #pragma unroll
            for (int nt = 0; nt < 4; ++nt) {
                uint4 b = __ldg(bptr + ((size_t)nt * NKS + kks) * 32);
                #pragma unroll
                for (int mt = 0; mt < 2; ++mt) {
                    mma16816(acc[mt][nt], ahi[mt], b.x, b.y);   // Ahi*Bhi
                    mma16816(acc[mt][nt], ahi[mt], b.z, b.w);   // Ahi*Blo
                    mma16816(acc[mt][nt], alo[mt], b.x, b.y);   // Alo*Bhi
                }
            }
        }

        __syncthreads();
        if (c + 1 < NCHUNK) {
            store_chunk(1 - buf, (c + 1) * 64);
            __syncthreads();
        }
    }

    // ---- epilogue: c-frag rows lane>>2 (+8), cols (lane&3)*2 (+1)
    #pragma unroll
    for (int mt = 0; mt < 2; ++mt) {
        int r0 = rowBase + warp_m * 32 + mt * 16 + (lane >> 2);
        #pragma unroll
        for (int nt = 0; nt < 4; ++nt) {
            int col = warp_n * 32 + nt * 8 + (lane & 3) * 2;
            float v0 = acc[mt][nt][0], v1 = acc[mt][nt][1];
            float v2 = acc[mt][nt][2], v3 = acc[mt][nt][3];
            if (KIND == 1) {
                float b0 = __ldg(bias + col), b1 = __ldg(bias + col + 1);
                v0 = fmaxf(v0 + b0, 0.f); v1 = fmaxf(v1 + b1, 0.f);
                v2 = fmaxf(v2 + b0, 0.f); v3 = fmaxf(v3 + b1, 0.f);
            }
            float* dst = (KIND == 1) ? g_h : g_c2;
            if (r0 < N_NODES)
                *(float2*)(dst + (size_t)r0 * 128 + col) = make_float2(v0, v1);
            if (r0 + 8 < N_NODES)
                *(float2*)(dst + (size_t)(r0 + 8) * 128 + col) = make_float2(v2, v3);
        }
    }
}

__global__ void __launch_bounds__(256, 2) gemm1_mma(const float* __restrict__ x,
                                                    const float* __restrict__ b1) {
    gemm_mma_body<1>(x, gW1frag, b1);
}
__global__ void __launch_bounds__(256, 2) gemm2_mma() {
    gemm_mma_body<2>(nullptr, gW2frag, nullptr);
}

// ---------------------------------------------------------------------------
__global__ void final_kernel(float* __restrict__ out, const float* __restrict__ b2) {
    int i = blockIdx.x * blockDim.x + threadIdx.x;
    if (i >= N_NODES * OUT_C) return;
    int n = i >> 6, j = i & 63;
    float d = fmaxf(g_deg[n], 1.0f);
    out[i] = g_msg2[i] / d + __ldg(b2 + j) + g_c2[(size_t)n * 128 + 64 + j];
}

// ---------------------------------------------------------------------------
extern "C" void kernel_launch(void* const* d_in, const int* in_sizes, int n_in,
                              void* d_out, int out_size) {
    const float* x   = (const float*)d_in[0];
    const int*   ei  = (const int*)d_in[1];
    const float* W1l = (const float*)d_in[2];
    const float* b1  = (const float*)d_in[3];
    const float* W1r = (const float*)d_in[4];
    const float* W2l = (const float*)d_in[5];
    const float* b2  = (const float*)d_in[6];
    const float* W2r = (const float*)d_in[7];
    float* out = (float*)d_out;

    zero_kernel<<<2048, 256>>>();
    prep_weights<<<48, 256>>>(W1l, W1r, W2l, W2r);
    scatter1_kernel<<<(N_EDGES * 32) / 256, 256>>>(x, ei);

    const int gemmBlocks = (N_NODES + 63) / 64;   // 782
    gemm1_mma<<<gemmBlocks, 256>>>(x, b1);
    gemm2_mma<<<gemmBlocks, 256>>>();

    scatter2_kernel<<<(N_EDGES * 16) / 256, 256>>>(ei);
    final_kernel<<<(N_NODES * OUT_C + 255) / 256, 256>>>(out, b2);
}

// round 6
// speedup vs baseline: 2.2489x; 1.6385x over previous
#include <cuda_runtime.h>
#include <cuda_bf16.h>
#include <cstdint>

// ---------------------------------------------------------------------------
// SAGE 2-layer forward, GB300 (ptxas target sm_103 baseline: no tcgen05).
//   GEMMs: mma.sync m16n8k16 bf16 hi/lo split (AhBh+AhBl+AlBh), fp32 acc.
//   Aggregation: CSR (hist -> scan -> fill) + warp-per-node gather. No atics
//   on the feature payload, no zero pass, epilogues fused into the agg kernels.
// edge_index is int32 on device.
// ---------------------------------------------------------------------------

#define N_NODES 50000
#define N_EDGES 800000
#define IN_C    128
#define HID_C   128
#define OUT_C   64
#define NB      196            // scan blocks: 196*256 = 50176 >= N_NODES

__device__ __align__(16) float g_msg1[(size_t)N_NODES * HID_C];   // mean-agg(x)
__device__ __align__(16) float g_h   [(size_t)N_NODES * HID_C];
__device__ __align__(16) float g_c2  [(size_t)N_NODES * 128];     // [t=h@W2l | hr=h@W2r]

__device__ int g_deg_i[NB * 256];
__device__ int g_off  [NB * 256];
__device__ int g_cur  [NB * 256];
__device__ int g_bsum [NB];
__device__ int g_csr  [950016];   // padded-deg capacity: 800000 + 3*50000

// Precomputed B fragments: uint4 {bh0, bh1, bl0, bl1} per (n_tile, ks, lane).
__device__ __align__(16) uint4 gW1frag[16 * 16 * 32];
__device__ __align__(16) uint4 gW2frag[16 * 8 * 32];

// ---------------- helpers ----------------------------------------------------
__device__ __forceinline__ uint32_t smem_u32(const void* p) {
    uint32_t a;
    asm("{ .reg .u64 t; cvta.to.shared.u64 t, %1; cvt.u32.u64 %0, t; }" : "=r"(a) : "l"(p));
    return a;
}
__device__ __forceinline__ void split2(float f0, float f1, uint32_t& hi, uint32_t& lo) {
    __nv_bfloat16 h0 = __float2bfloat16(f0);
    __nv_bfloat16 h1 = __float2bfloat16(f1);
    __nv_bfloat16 l0 = __float2bfloat16(f0 - __bfloat162float(h0));
    __nv_bfloat16 l1 = __float2bfloat16(f1 - __bfloat162float(h1));
    hi = ((uint32_t)__bfloat16_as_ushort(h1) << 16) | __bfloat16_as_ushort(h0);
    lo = ((uint32_t)__bfloat16_as_ushort(l1) << 16) | __bfloat16_as_ushort(l0);
}
__device__ __forceinline__ void ldsm4(uint32_t* r, uint32_t addr) {
    asm volatile("ldmatrix.sync.aligned.m8n8.x4.shared.b16 {%0,%1,%2,%3}, [%4];"
                 : "=r"(r[0]), "=r"(r[1]), "=r"(r[2]), "=r"(r[3]) : "r"(addr));
}
__device__ __forceinline__ void mma16816(float* d, const uint32_t* a, uint32_t b0, uint32_t b1) {
    asm volatile(
        "mma.sync.aligned.m16n8k16.row.col.f32.bf16.bf16.f32 "
        "{%0,%1,%2,%3}, {%4,%5,%6,%7}, {%8,%9}, {%0,%1,%2,%3};"
        : "+f"(d[0]), "+f"(d[1]), "+f"(d[2]), "+f"(d[3])
        : "r"(a[0]), "r"(a[1]), "r"(a[2]), "r"(a[3]), "r"(b0), "r"(b1));
}

// ---------------------------------------------------------------------------
// CSR build
// ---------------------------------------------------------------------------
__global__ void zero_deg() {
    int n = blockIdx.x * blockDim.x + threadIdx.x;
    if (n < NB * 256) g_deg_i[n] = 0;
}
__global__ void hist_kernel(const int* __restrict__ ei) {
    int e = blockIdx.x * blockDim.x + threadIdx.x;
    if (e >= N_EDGES) return;
    int src = __ldg(ei + e);
    int dst = __ldg(ei + N_EDGES + e);
    if ((unsigned)src >= N_NODES || (unsigned)dst >= N_NODES) return;
    atomicAdd(&g_deg_i[dst], 1);
}
// block-local exclusive scan of padded degrees
__global__ void scan1_kernel() {
    __shared__ int s[256];
    int t = threadIdx.x;
    int n = blockIdx.x * 256 + t;
    int v = 0;
    if (n < N_NODES) v = (g_deg_i[n] + 3) & ~3;   // pad each region to 16B
    s[t] = v;
    __syncthreads();
    #pragma unroll
    for (int d = 1; d < 256; d <<= 1) {
        int add = (t >= d) ? s[t - d] : 0;
        __syncthreads();
        s[t] += add;
        __syncthreads();
    }
    g_off[n] = s[t] - v;                 // exclusive
    if (t == 255) g_bsum[blockIdx.x] = s[255];
}
__global__ void scan2_kernel() {
    __shared__ int s[256];
    int t = threadIdx.x;
    int v = (t < NB) ? g_bsum[t] : 0;
    s[t] = v;
    __syncthreads();
    #pragma unroll
    for (int d = 1; d < 256; d <<= 1) {
        int add = (t >= d) ? s[t - d] : 0;
        __syncthreads();
        s[t] += add;
        __syncthreads();
    }
    if (t < NB) g_bsum[t] = s[t] - v;    // exclusive
}
__global__ void scan3_kernel() {
    int n = blockIdx.x * 256 + threadIdx.x;
    int o = g_off[n] + g_bsum[blockIdx.x];
    g_off[n] = o;
    g_cur[n] = o;
}
__global__ void fill_kernel(const int* __restrict__ ei) {
    int e = blockIdx.x * blockDim.x + threadIdx.x;
    if (e >= N_EDGES) return;
    int src = __ldg(ei + e);
    int dst = __ldg(ei + N_EDGES + e);
    if ((unsigned)src >= N_NODES || (unsigned)dst >= N_NODES) return;
    int pos = atomicAdd(&g_cur[dst], 1);
    g_csr[pos] = src;
}

// ---------------------------------------------------------------------------
// agg1: msg1[n] = mean of x[src] over incoming edges (warp per node, d=128)
// ---------------------------------------------------------------------------
__global__ void __launch_bounds__(256) agg1_kernel(const float* __restrict__ x) {
    int w    = (blockIdx.x * blockDim.x + threadIdx.x) >> 5;
    int lane = threadIdx.x & 31;
    if (w >= N_NODES) return;
    int deg = g_deg_i[w];
    int off = g_off[w];
    float4 acc = make_float4(0.f, 0.f, 0.f, 0.f);
    int i = 0;
    for (; i + 4 <= deg; i += 4) {
        int4 s4 = __ldg((const int4*)(g_csr + off + i));   // off is 4-aligned
        float4 v0 = __ldg((const float4*)(x + (size_t)s4.x * 128) + lane);
        float4 v1 = __ldg((const float4*)(x + (size_t)s4.y * 128) + lane);
        float4 v2 = __ldg((const float4*)(x + (size_t)s4.z * 128) + lane);
        float4 v3 = __ldg((const float4*)(x + (size_t)s4.w * 128) + lane);
        acc.x += v0.x + v1.x + v2.x + v3.x;
        acc.y += v0.y + v1.y + v2.y + v3.y;
        acc.z += v0.z + v1.z + v2.z + v3.z;
        acc.w += v0.w + v1.w + v2.w + v3.w;
    }
    for (; i < deg; ++i) {
        int s = __ldg(g_csr + off + i);
        float4 v = __ldg((const float4*)(x + (size_t)s * 128) + lane);
        acc.x += v.x; acc.y += v.y; acc.z += v.z; acc.w += v.w;
    }
    float rd = 1.0f / fmaxf((float)deg, 1.0f);
    acc.x *= rd; acc.y *= rd; acc.z *= rd; acc.w *= rd;
    *((float4*)(g_msg1 + (size_t)w * 128) + lane) = acc;
}

// ---------------------------------------------------------------------------
// agg2 + final epilogue: out[n] = mean(t[src]) + b2 + hr[n]   (d=64, float2/lane)
// t = g_c2 cols [0,64), hr = g_c2 cols [64,128)
// ---------------------------------------------------------------------------
__global__ void __launch_bounds__(256) agg2_kernel(float* __restrict__ out,
                                                   const float* __restrict__ b2) {
    int w    = (blockIdx.x * blockDim.x + threadIdx.x) >> 5;
    int lane = threadIdx.x & 31;
    if (w >= N_NODES) return;
    int deg = g_deg_i[w];
    int off = g_off[w];
    float2 acc = make_float2(0.f, 0.f);
    int i = 0;
    for (; i + 4 <= deg; i += 4) {
        int4 s4 = __ldg((const int4*)(g_csr + off + i));
        float2 v0 = __ldg((const float2*)(g_c2 + (size_t)s4.x * 128) + lane);
        float2 v1 = __ldg((const float2*)(g_c2 + (size_t)s4.y * 128) + lane);
        float2 v2 = __ldg((const float2*)(g_c2 + (size_t)s4.z * 128) + lane);
        float2 v3 = __ldg((const float2*)(g_c2 + (size_t)s4.w * 128) + lane);
        acc.x += v0.x + v1.x + v2.x + v3.x;
        acc.y += v0.y + v1.y + v2.y + v3.y;
    }
    for (; i < deg; ++i) {
        int s = __ldg(g_csr + off + i);
        float2 v = __ldg((const float2*)(g_c2 + (size_t)s * 128) + lane);
        acc.x += v.x; acc.y += v.y;
    }
    float rd = 1.0f / fmaxf((float)deg, 1.0f);
    float2 hr = *((const float2*)(g_c2 + (size_t)w * 128 + 64) + lane);
    float2 bb = __ldg((const float2*)b2 + lane);
    float2 o;
    o.x = acc.x * rd + bb.x + hr.x;
    o.y = acc.y * rd + bb.y + hr.y;
    *((float2*)(out + (size_t)w * 64) + lane) = o;
}

// ---------------------------------------------------------------------------
// Build MMA-ready B fragments (as round 5).
// ---------------------------------------------------------------------------
__global__ void prep_weights(const float* __restrict__ W1l, const float* __restrict__ W1r,
                             const float* __restrict__ W2l, const float* __restrict__ W2r) {
    int idx = blockIdx.x * blockDim.x + threadIdx.x;
    int total1 = 16 * 16 * 32;
    int total2 = 16 * 8 * 32;
    if (idx < total1) {
        int lane = idx & 31;
        int ks   = (idx >> 5) & 15;
        int ntl  = idx >> 9;
        int n  = ntl * 8 + (lane >> 2);
        int k0 = ks * 16 + (lane & 3) * 2;
        float f[4];
        #pragma unroll
        for (int q = 0; q < 4; ++q) {
            int k = k0 + (q >> 1) * 8 + (q & 1);
            f[q] = (k < 128) ? __ldg(W1l + (size_t)k * 128 + n)
                             : __ldg(W1r + (size_t)(k - 128) * 128 + n);
        }
        uint4 r;
        split2(f[0], f[1], r.x, r.z);
        split2(f[2], f[3], r.y, r.w);
        gW1frag[idx] = r;
    } else if (idx < total1 + total2) {
        int j = idx - total1;
        int lane = j & 31;
        int ks   = (j >> 5) & 7;
        int ntl  = j >> 8;
        int n  = ntl * 8 + (lane >> 2);
        int k0 = ks * 16 + (lane & 3) * 2;
        float f[4];
        #pragma unroll
        for (int q = 0; q < 4; ++q) {
            int k = k0 + (q >> 1) * 8 + (q & 1);
            f[q] = (n < 64) ? __ldg(W2l + (size_t)k * 64 + n)
                            : __ldg(W2r + (size_t)k * 64 + (n - 64));
        }
        uint4 r;
        split2(f[0], f[1], r.x, r.z);
        split2(f[2], f[3], r.y, r.w);
        gW2frag[j] = r;
    }
}

// ---------------------------------------------------------------------------
// Tensor-core GEMM: 64(M) x 128(N) CTA tile, 256 thr, 8 warps, double-buffered.
// KIND 1: A = [msg1 | x] (K=256), epilogue bias+relu -> g_h   (msg1 pre-divided)
// KIND 2: A = g_h (K=128),       epilogue raw       -> g_c2
// ---------------------------------------------------------------------------
#define A_STRIDE 72   // bf16 per smem row (144B -> ldmatrix conflict-free)

template <int KIND>
__device__ __forceinline__ void gemm_mma_body(const float* __restrict__ xin,
                                              const uint4* __restrict__ Bfrag,
                                              const float* __restrict__ bias) {
    constexpr int K_TOTAL = (KIND == 1) ? 256 : 128;
    constexpr int NKS     = K_TOTAL / 16;
    constexpr int NCHUNK  = K_TOTAL / 64;

    __shared__ __nv_bfloat16 sAhi[2][64 * A_STRIDE];
    __shared__ __nv_bfloat16 sAlo[2][64 * A_STRIDE];

    const int tid    = threadIdx.x;
    const int wid    = tid >> 5;
    const int lane   = tid & 31;
    const int warp_m = wid & 1;
    const int warp_n = wid >> 1;
    const int rowBase = blockIdx.x * 64;

    float4 pf[4];
    auto load_chunk = [&](int kb) {
        #pragma unroll
        for (int it = 0; it < 4; ++it) {
            int fid = tid + it * 256;
            int row = fid >> 4;
            int c4  = fid & 15;
            int gr  = rowBase + row;
            float4 v = make_float4(0.f, 0.f, 0.f, 0.f);
            if (gr < N_NODES) {
                if (KIND == 1) {
                    if (kb < 128)
                        v = *(const float4*)(g_msg1 + (size_t)gr * 128 + kb + c4 * 4);
                    else
                        v = __ldg((const float4*)(xin + (size_t)gr * 128 + (kb - 128) + c4 * 4));
                } else {
                    v = *(const float4*)(g_h + (size_t)gr * 128 + kb + c4 * 4);
                }
            }
            pf[it] = v;
        }
    };
    auto store_chunk = [&](int buf) {
        #pragma unroll
        for (int it = 0; it < 4; ++it) {
            int fid = tid + it * 256;
            int row = fid >> 4;
            int c4  = fid & 15;
            float4 v = pf[it];
            uint32_t h01, l01, h23, l23;
            split2(v.x, v.y, h01, l01);
            split2(v.z, v.w, h23, l23);
            int eoff = row * A_STRIDE + c4 * 4;
            *(uint32_t*)((char*)sAhi[buf] + eoff * 2)     = h01;
            *(uint32_t*)((char*)sAhi[buf] + eoff * 2 + 4) = h23;
            *(uint32_t*)((char*)sAlo[buf] + eoff * 2)     = l01;
            *(uint32_t*)((char*)sAlo[buf] + eoff * 2 + 4) = l23;
        }
    };

    float acc[2][4][4];
    #pragma unroll
    for (int mt = 0; mt < 2; ++mt)
        #pragma unroll
        for (int nt = 0; nt < 4; ++nt)
            #pragma unroll
            for (int q = 0; q < 4; ++q) acc[mt][nt][q] = 0.f;

    load_chunk(0);
    store_chunk(0);
    __syncthreads();

    const uint4* bptr = Bfrag + ((size_t)warp_n * 4 * NKS) * 32 + lane;

    for (int c = 0; c < NCHUNK; ++c) {
        int buf = c & 1;
        if (c + 1 < NCHUNK) load_chunk((c + 1) * 64);

        const uint32_t sAhi_u = smem_u32(sAhi[buf]);
        const uint32_t sAlo_u = smem_u32(sAlo[buf]);

        #pragma unroll
        for (int ks = 0; ks < 4; ++ks) {
            int kks = c * 4 + ks;
            uint32_t ahi[2][4], alo[2][4];
            #pragma unroll
            for (int mt = 0; mt < 2; ++mt) {
                int row = warp_m * 32 + mt * 16 + (lane & 15);
                int koff = ks * 16 + (lane >> 4) * 8;
                uint32_t byteoff = (uint32_t)(row * A_STRIDE + koff) * 2;
                ldsm4(ahi[mt], sAhi_u + byteoff);
                ldsm4(alo[mt], sAlo_u + byteoff);
            }
            #pragma unroll
            for (int nt = 0; nt < 4; ++nt) {
                uint4 b = __ldg(bptr + ((size_t)nt * NKS + kks) * 32);
                #pragma unroll
                for (int mt = 0; mt < 2; ++mt) {
                    mma16816(acc[mt][nt], ahi[mt], b.x, b.y);
                    mma16816(acc[mt][nt], ahi[mt], b.z, b.w);
                    mma16816(acc[mt][nt], alo[mt], b.x, b.y);
                }
            }
        }

        __syncthreads();
        if (c + 1 < NCHUNK) {
            store_chunk(1 - buf);
            __syncthreads();
        }
    }

    #pragma unroll
    for (int mt = 0; mt < 2; ++mt) {
        int r0 = rowBase + warp_m * 32 + mt * 16 + (lane >> 2);
        #pragma unroll
        for (int nt = 0; nt < 4; ++nt) {
            int col = warp_n * 32 + nt * 8 + (lane & 3) * 2;
            float v0 = acc[mt][nt][0], v1 = acc[mt][nt][1];
            float v2 = acc[mt][nt][2], v3 = acc[mt][nt][3];
            if (KIND == 1) {
                float b0 = __ldg(bias + col), b1 = __ldg(bias + col + 1);
                v0 = fmaxf(v0 + b0, 0.f); v1 = fmaxf(v1 + b1, 0.f);
                v2 = fmaxf(v2 + b0, 0.f); v3 = fmaxf(v3 + b1, 0.f);
            }
            float* dst = (KIND == 1) ? g_h : g_c2;
            if (r0 < N_NODES)
                *(float2*)(dst + (size_t)r0 * 128 + col) = make_float2(v0, v1);
            if (r0 + 8 < N_NODES)
                *(float2*)(dst + (size_t)(r0 + 8) * 128 + col) = make_float2(v2, v3);
        }
    }
}

__global__ void __launch_bounds__(256, 2) gemm1_mma(const float* __restrict__ x,
                                                    const float* __restrict__ b1) {
    gemm_mma_body<1>(x, gW1frag, b1);
}
__global__ void __launch_bounds__(256, 2) gemm2_mma() {
    gemm_mma_body<2>(nullptr, gW2frag, nullptr);
}

// ---------------------------------------------------------------------------
extern "C" void kernel_launch(void* const* d_in, const int* in_sizes, int n_in,
                              void* d_out, int out_size) {
    const float* x   = (const float*)d_in[0];
    const int*   ei  = (const int*)d_in[1];
    const float* W1l = (const float*)d_in[2];
    const float* b1  = (const float*)d_in[3];
    const float* W1r = (const float*)d_in[4];
    const float* W2l = (const float*)d_in[5];
    const float* b2  = (const float*)d_in[6];
    const float* W2r = (const float*)d_in[7];
    float* out = (float*)d_out;

    const int EB = (N_EDGES + 255) / 256;          // 3125

    zero_deg<<<NB, 256>>>();
    prep_weights<<<48, 256>>>(W1l, W1r, W2l, W2r);
    hist_kernel<<<EB, 256>>>(ei);
    scan1_kernel<<<NB, 256>>>();
    scan2_kernel<<<1, 256>>>();
    scan3_kernel<<<NB, 256>>>();
    fill_kernel<<<EB, 256>>>(ei);

    agg1_kernel<<<(N_NODES * 32 + 255) / 256, 256>>>(x);

    const int gemmBlocks = (N_NODES + 63) / 64;    // 782
    gemm1_mma<<<gemmBlocks, 256>>>(x, b1);
    gemm2_mma<<<gemmBlocks, 256>>>();

    agg2_kernel<<<(N_NODES * 32 + 255) / 256, 256>>>(out, b2);
}